// round 15
// baseline (speedup 1.0000x reference)
#include <cuda_runtime.h>
#include <cuda_bf16.h>
#include <math.h>

// Detector: per-submap (1024 pts) -> top-512 by xy-dist -> FPS 32 -> MLP gather.
// K1: register-resident radix-select (float4 loads, 4-region hist, fused packed scan) [round-13].
// K2: 2 warps/submap packed-f32x2 FPS (8 pts/lane) + MLP split across both warps; PDL launch.

#define NPTS 1024
#define KPOS 512
#define KSEL 32
#define T1   256
#define BMAX 2048

#define W1_OFF 0
#define B1_OFF 512
#define W2_OFF 528
#define B2_OFF 656
#define W3_OFF 664
#define B3_OFF 672
#define WTOT   673

typedef unsigned long long u64;
typedef unsigned int u32;

__device__ float4 g_selp[(size_t)BMAX * KPOS];
__device__ int    g_start[BMAX];

__device__ __forceinline__ u64 umax64(u64 a, u64 b) { return a > b ? a : b; }
__device__ __forceinline__ u64 umin64(u64 a, u64 b) { return a < b ? a : b; }

__device__ __forceinline__ u64 shfl_xor_u64(u64 v, int m) {
    u32 lo = __shfl_xor_sync(0xffffffffu, (u32)v, m);
    u32 hi = __shfl_xor_sync(0xffffffffu, (u32)(v >> 32), m);
    return ((u64)hi << 32) | lo;
}

#define PACK_F32X2(out, lo, hi) \
    asm("mov.b64 %0, {%1, %2};" : "=l"(out) : "r"(lo), "r"(hi))
#define ADD_F32X2(out, a, b) \
    asm("add.rn.f32x2 %0, %1, %2;" : "=l"(out) : "l"(a), "l"(b))
#define MUL_F32X2(out, a, b) \
    asm("mul.rn.f32x2 %0, %1, %2;" : "=l"(out) : "l"(a), "l"(b))

// ---------------- K1: select top-512 + compact (round-13) ----------------
__global__ __launch_bounds__(T1) void select_kernel(const float* __restrict__ pos)
{
    __shared__ u32 hist[4][256];
    __shared__ u32 warpsum[8];
    __shared__ u64 warpkey[8];
    __shared__ u32 bcast[2];

    const int b = blockIdx.x, t = threadIdx.x;
    const int lane = t & 31, w = t >> 5;
    const size_t base = (size_t)b * NPTS;
    const unsigned FULL = 0xffffffffu;

    {
        u32* h = (u32*)hist;
        #pragma unroll
        for (int j = 0; j < 4; j++) h[j * T1 + t] = 0;
    }

    const int i0 = t * 4;
    float fpx[4], fpy[4], fpz[4];
    {
        const float4* p4 = (const float4*)(pos + base * 3);
        float4 q0 = p4[t * 3 + 0];
        float4 q1 = p4[t * 3 + 1];
        float4 q2 = p4[t * 3 + 2];
        fpx[0] = q0.x; fpy[0] = q0.y; fpz[0] = q0.z;
        fpx[1] = q0.w; fpy[1] = q1.x; fpz[1] = q1.y;
        fpx[2] = q1.z; fpy[2] = q1.w; fpz[2] = q2.x;
        fpx[3] = q2.y; fpy[3] = q2.z; fpz[3] = q2.w;
    }
    u32 v[4];
    #pragma unroll
    for (int j = 0; j < 4; j++)
        v[j] = __float_as_uint(__fsqrt_rn(__fadd_rn(__fmul_rn(fpx[j], fpx[j]),
                                                    __fmul_rn(fpy[j], fpy[j]))));
    __syncthreads();

    u32 r = 511, prefix = 0;
    const u32 himask_tab[4] = {0u, 0xFF000000u, 0xFFFF0000u, 0xFFFFFF00u};
    #pragma unroll
    for (int pass = 0; pass < 4; pass++) {
        const int shift = 24 - 8 * pass;
        const u32 hm = himask_tab[pass];
        #pragma unroll
        for (int j = 0; j < 4; j++)
            if ((v[j] & hm) == (prefix & hm)) atomicAdd(&hist[pass][(v[j] >> shift) & 255], 1);
        __syncthreads();
        if (t < 32) {
            u32 c[8], ssum = 0;
            #pragma unroll
            for (int j = 0; j < 8; j++) { c[j] = hist[pass][t * 8 + j]; ssum += c[j]; }
            u32 incl = ssum;
            #pragma unroll
            for (int o = 1; o < 32; o <<= 1) {
                u32 n = __shfl_up_sync(FULL, incl, o);
                if (lane >= o) incl += n;
            }
            u32 excl = incl - ssum;
            if (r >= excl && r < incl) {
                u32 run = excl;
                #pragma unroll
                for (int j = 0; j < 8; j++) {
                    if (r < run + c[j]) { bcast[0] = (u32)(t * 8 + j); bcast[1] = r - run; break; }
                    run += c[j];
                }
            }
        }
        __syncthreads();
        prefix |= bcast[0] << shift;
        r = bcast[1];
    }
    const u32 D = prefix;

    u32 f[4], lt[4];
    u32 cnt = 0;
    #pragma unroll
    for (int j = 0; j < 4; j++) {
        f[j]  = (v[j] == D);
        lt[j] = (v[j] < D);
        cnt += (f[j] << 16) | lt[j];
    }
    u32 incl = cnt;
    #pragma unroll
    for (int o = 1; o < 32; o <<= 1) {
        u32 n = __shfl_up_sync(FULL, incl, o);
        if (lane >= o) incl += n;
    }
    if (lane == 31) warpsum[w] = incl;
    __syncthreads();
    if (t == 0) { u32 run = 0; for (int j = 0; j < 8; j++) { u32 tmp = warpsum[j]; warpsum[j] = run; run += tmp; } }
    __syncthreads();
    u32 excl = warpsum[w] + (incl - cnt);
    u32 pf  = excl >> 16;
    u32 plt = excl & 0xFFFFu;

    float4* outp = g_selp + (size_t)b * KPOS;
    u64 key = 0xFFFFFFFFFFFFFFFFull;
    #pragma unroll
    for (int j = 0; j < 4; j++) {
        u32 m = lt[j] | (f[j] & (pf <= r));
        if (m) {
            u32 slot = plt + min(pf, r + 1u);
            outp[slot] = make_float4(fpx[j], fpy[j], fpz[j], (float)(i0 + j));
            key = umin64(key, ((u64)v[j] << 32) | slot);
        }
        pf += f[j];
        plt += lt[j];
    }
    #pragma unroll
    for (int o = 16; o >= 1; o >>= 1)
        key = umin64(key, shfl_xor_u64(key, o));
    if (lane == 0) warpkey[w] = key;
    __syncthreads();
    if (t == 0) {
        u64 k = warpkey[0];
        #pragma unroll
        for (int j = 1; j < 8; j++) k = umin64(k, warpkey[j]);
        g_start[b] = (int)(u32)k;
    }
}

// ---------------- K2: FPS (2 warps) + MLP split across both warps; PDL ----------------
__global__ __launch_bounds__(64) void fps_mlp_kernel(
    const float* __restrict__ x,
    const float* __restrict__ W1, const float* __restrict__ b1,
    const float* __restrict__ W2, const float* __restrict__ b2,
    const float* __restrict__ W3, const float* __restrict__ b3,
    float* __restrict__ out_w, float* __restrict__ out_i)
{
    __shared__ float4 selp[KPOS];
    __shared__ int chosen[KSEL];
    __shared__ float wsh[WTOT];
    __shared__ u64 sred[2][2];
    __shared__ float sh1[KSEL][17];   // padded: paired threads read same row
    __shared__ float sh2[KSEL][9];

    const int b = blockIdx.x;
    const int t = threadIdx.x;
    const int l = t & 31, w = t >> 5;
    const unsigned FULL = 0xffffffffu;

    for (int i = t; i < WTOT; i += 64) {
        float v;
        if (i < B1_OFF)       v = W1[i];
        else if (i < W2_OFF)  v = b1[i - B1_OFF];
        else if (i < B2_OFF)  v = W2[i - W2_OFF];
        else if (i < W3_OFF)  v = b2[i - B2_OFF];
        else if (i < B3_OFF)  v = W3[i - W3_OFF];
        else                  v = b3[0];
        wsh[i] = v;
    }

    cudaGridDependencySynchronize();

    float fx[8], fy[8], fz[8];
    #pragma unroll
    for (int m = 0; m < 8; m++) {
        int slot = (w << 8) + (m << 5) + l;
        float4 f = g_selp[(size_t)b * KPOS + slot];
        selp[slot] = f;
        fx[m] = f.x; fy[m] = f.y; fz[m] = f.z;
    }
    u64 PX[4], PY[4], PZ[4];
    #pragma unroll
    for (int p = 0; p < 4; p++) {
        PACK_F32X2(PX[p], __float_as_uint(fx[2 * p]), __float_as_uint(fx[2 * p + 1]));
        PACK_F32X2(PY[p], __float_as_uint(fy[2 * p]), __float_as_uint(fy[2 * p + 1]));
        PACK_F32X2(PZ[p], __float_as_uint(fz[2 * p]), __float_as_uint(fz[2 * p + 1]));
    }
    __syncthreads();

    const int sslot = g_start[b];
    float4 p0 = selp[sslot];
    if (t == 0) {
        out_i[(size_t)b * KSEL + 0] = p0.w;
        chosen[0] = (int)p0.w;
    }

    u64 NX, NY, NZ;
    {
        u32 nx = __float_as_uint(-p0.x), ny = __float_as_uint(-p0.y), nz = __float_as_uint(-p0.z);
        PACK_F32X2(NX, nx, nx); PACK_F32X2(NY, ny, ny); PACK_F32X2(NZ, nz, nz);
    }
    u64 md[4];
    #pragma unroll
    for (int p = 0; p < 4; p++) {
        u64 dx, dy, dz, xx, yy, zz, s1, s2;
        ADD_F32X2(dx, PX[p], NX); ADD_F32X2(dy, PY[p], NY); ADD_F32X2(dz, PZ[p], NZ);
        MUL_F32X2(xx, dx, dx); MUL_F32X2(yy, dy, dy); MUL_F32X2(zz, dz, dz);
        ADD_F32X2(s1, xx, yy); ADD_F32X2(s2, s1, zz);
        md[p] = s2;
    }

    const u32 rc = 511u - (u32)(w * 256) - (u32)l;

    for (int it = 1; it < KSEL; ++it) {
        u32 bl0 = (u32)md[0], bh0 = (u32)(md[0] >> 32);
        u32 bl1 = (u32)md[1], bh1 = (u32)(md[1] >> 32);
        u32 bl2 = (u32)md[2], bh2 = (u32)(md[2] >> 32);
        u32 bl3 = (u32)md[3], bh3 = (u32)(md[3] >> 32);
        u32 a0 = max(bl0, bh0), a1 = max(bl1, bh1), a2 = max(bl2, bh2), a3 = max(bl3, bh3);
        u32 lmax = max(max(a0, a1), max(a2, a3));
        u32 wmax = __reduce_max_sync(FULL, lmax);

        u32 c0 = (bl0 == wmax) ? (rc - 0)   : 0u;
        u32 c1 = (bh0 == wmax) ? (rc - 32)  : 0u;
        u32 c2 = (bl1 == wmax) ? (rc - 64)  : 0u;
        u32 c3 = (bh1 == wmax) ? (rc - 96)  : 0u;
        u32 c4 = (bl2 == wmax) ? (rc - 128) : 0u;
        u32 c5 = (bh2 == wmax) ? (rc - 160) : 0u;
        u32 c6 = (bl3 == wmax) ? (rc - 192) : 0u;
        u32 c7 = (bh3 == wmax) ? (rc - 224) : 0u;
        u32 cm = max(max(max(c0, c1), max(c2, c3)), max(max(c4, c5), max(c6, c7)));
        u32 wcand = __reduce_max_sync(FULL, cm);

        if (l == 0) sred[w][it & 1] = ((u64)wmax << 32) | wcand;
        __syncthreads();
        u64 best = umax64(sred[0][it & 1], sred[1][it & 1]);
        int sel = 511 - (int)(u32)best;

        float4 c = selp[sel];
        if (t == 0) {
            out_i[(size_t)b * KSEL + it] = c.w;
            chosen[it] = (int)c.w;
        }

        u32 nx = __float_as_uint(-c.x), ny = __float_as_uint(-c.y), nz = __float_as_uint(-c.z);
        PACK_F32X2(NX, nx, nx); PACK_F32X2(NY, ny, ny); PACK_F32X2(NZ, nz, nz);
        #pragma unroll
        for (int p = 0; p < 4; p++) {
            u64 dx, dy, dz, xx, yy, zz, s1, s2;
            ADD_F32X2(dx, PX[p], NX); ADD_F32X2(dy, PY[p], NY); ADD_F32X2(dz, PZ[p], NZ);
            MUL_F32X2(xx, dx, dx); MUL_F32X2(yy, dy, dy); MUL_F32X2(zz, dz, dz);
            ADD_F32X2(s1, xx, yy); ADD_F32X2(s2, s1, zz);
            u32 mlo = min((u32)md[p], (u32)s2);
            u32 mhi = min((u32)(md[p] >> 32), (u32)(s2 >> 32));
            md[p] = ((u64)mhi << 32) | mlo;
        }
    }
    __syncthreads();

    // ---- MLP + softplus, split across both warps; per-neuron fmaf chains bit-identical ----
    {
        const int sid = t & 31, half = t >> 5;
        int orig = chosen[sid];
        const float4* xr4 = (const float4*)(x + ((size_t)b * NPTS + orig) * 32);
        float xv[32];
        #pragma unroll
        for (int i = 0; i < 8; i++) {
            float4 q = xr4[i];
            xv[4 * i] = q.x; xv[4 * i + 1] = q.y; xv[4 * i + 2] = q.z; xv[4 * i + 3] = q.w;
        }

        // phase 1: half h computes h1 neurons [8h, 8h+8)
        #pragma unroll
        for (int oo = 0; oo < 8; oo++) {
            int o = half * 8 + oo;
            float a = wsh[B1_OFF + o];
            #pragma unroll
            for (int i = 0; i < 32; i++) a = fmaf(xv[i], wsh[W1_OFF + i * 16 + o], a);
            sh1[sid][o] = fmaxf(a, 0.0f);
        }
        __syncthreads();

        // phase 2: half h computes h2 neurons [4h, 4h+4)
        #pragma unroll
        for (int oo = 0; oo < 4; oo++) {
            int o = half * 4 + oo;
            float a = wsh[B2_OFF + o];
            #pragma unroll
            for (int i = 0; i < 16; i++) a = fmaf(sh1[sid][i], wsh[W2_OFF + i * 8 + o], a);
            sh2[sid][o] = fmaxf(a, 0.0f);
        }
        __syncthreads();

        // phase 3: warp 0 finishes
        if (t < KSEL) {
            float s = wsh[B3_OFF];
            #pragma unroll
            for (int i = 0; i < 8; i++) s = fmaf(sh2[sid][i], wsh[W3_OFF + i], s);
            float sp = fmaxf(s, 0.0f) + log1pf(expf(-fabsf(s)));
            out_w[(size_t)b * KSEL + sid] = sp;
        }
    }
}

extern "C" void kernel_launch(void* const* d_in, const int* in_sizes, int n_in,
                              void* d_out, int out_size) {
    const float* x   = (const float*)d_in[0];
    const float* pos = (const float*)d_in[1];
    const float* W1  = (const float*)d_in[3];
    const float* b1  = (const float*)d_in[4];
    const float* W2  = (const float*)d_in[5];
    const float* b2  = (const float*)d_in[6];
    const float* W3  = (const float*)d_in[7];
    const float* b3  = (const float*)d_in[8];

    int n_points = in_sizes[0] / 32;      // B * 1024
    int B = n_points / NPTS;
    if (B > BMAX) B = BMAX;

    float* out_w = (float*)d_out;
    float* out_i = out_w + (size_t)B * KSEL;

    select_kernel<<<B, T1>>>(pos);

    cudaLaunchConfig_t cfg = {};
    cfg.gridDim = dim3((unsigned)B);
    cfg.blockDim = dim3(64);
    cfg.dynamicSmemBytes = 0;
    cfg.stream = 0;
    cudaLaunchAttribute attr[1];
    attr[0].id = cudaLaunchAttributeProgrammaticStreamSerialization;
    attr[0].val.programmaticStreamSerializationAllowed = 1;
    cfg.attrs = attr;
    cfg.numAttrs = 1;
    cudaLaunchKernelEx(&cfg, fps_mlp_kernel, x, W1, b1, W2, b2, W3, b3, out_w, out_i);
}

// round 16
// speedup vs baseline: 1.0494x; 1.0494x over previous
#include <cuda_runtime.h>
#include <cuda_bf16.h>
#include <math.h>

// Detector: per-submap (1024 pts) -> top-512 by xy-dist -> FPS 32 -> MLP gather.
// K1: register-resident radix-select [round-13] + static-control-flow singleton early exit
//     (skip remaining passes when the rank-511 bin count == 1).
// K2: 2 warps/submap packed-f32x2 FPS (8 pts/lane) + fused MLP [round-6/13 optimum], PDL launch.

#define NPTS 1024
#define KPOS 512
#define KSEL 32
#define T1   256
#define BMAX 2048

#define W1_OFF 0
#define B1_OFF 512
#define W2_OFF 528
#define B2_OFF 656
#define W3_OFF 664
#define B3_OFF 672
#define WTOT   673

typedef unsigned long long u64;
typedef unsigned int u32;

__device__ float4 g_selp[(size_t)BMAX * KPOS];
__device__ int    g_start[BMAX];

__device__ __forceinline__ u64 umax64(u64 a, u64 b) { return a > b ? a : b; }
__device__ __forceinline__ u64 umin64(u64 a, u64 b) { return a < b ? a : b; }

__device__ __forceinline__ u64 shfl_xor_u64(u64 v, int m) {
    u32 lo = __shfl_xor_sync(0xffffffffu, (u32)v, m);
    u32 hi = __shfl_xor_sync(0xffffffffu, (u32)(v >> 32), m);
    return ((u64)hi << 32) | lo;
}

#define PACK_F32X2(out, lo, hi) \
    asm("mov.b64 %0, {%1, %2};" : "=l"(out) : "r"(lo), "r"(hi))
#define ADD_F32X2(out, a, b) \
    asm("add.rn.f32x2 %0, %1, %2;" : "=l"(out) : "l"(a), "l"(b))
#define MUL_F32X2(out, a, b) \
    asm("mul.rn.f32x2 %0, %1, %2;" : "=l"(out) : "l"(a), "l"(b))

// ---------------- K1: select top-512 + compact ----------------
__global__ __launch_bounds__(T1) void select_kernel(const float* __restrict__ pos)
{
    __shared__ u32 hist[4][256];
    __shared__ u32 warpsum[8];
    __shared__ u64 warpkey[8];
    __shared__ u32 bcast[3];          // [byte, r, count]
    __shared__ u32 s_D;

    const int b = blockIdx.x, t = threadIdx.x;
    const int lane = t & 31, w = t >> 5;
    const size_t base = (size_t)b * NPTS;
    const unsigned FULL = 0xffffffffu;

    {
        u32* h = (u32*)hist;
        #pragma unroll
        for (int j = 0; j < 4; j++) h[j * T1 + t] = 0;
    }

    const int i0 = t * 4;
    float fpx[4], fpy[4], fpz[4];
    {
        const float4* p4 = (const float4*)(pos + base * 3);
        float4 q0 = p4[t * 3 + 0];
        float4 q1 = p4[t * 3 + 1];
        float4 q2 = p4[t * 3 + 2];
        fpx[0] = q0.x; fpy[0] = q0.y; fpz[0] = q0.z;
        fpx[1] = q0.w; fpy[1] = q1.x; fpz[1] = q1.y;
        fpx[2] = q1.z; fpy[2] = q1.w; fpz[2] = q2.x;
        fpx[3] = q2.y; fpy[3] = q2.z; fpz[3] = q2.w;
    }
    u32 v[4];
    #pragma unroll
    for (int j = 0; j < 4; j++)
        v[j] = __float_as_uint(__fsqrt_rn(__fadd_rn(__fmul_rn(fpx[j], fpx[j]),
                                                    __fmul_rn(fpy[j], fpy[j]))));
    __syncthreads();

    // radix select rank-511; singleton early exit (all control flow block-uniform, static shifts)
    u32 r = 511, prefix = 0;
    bool done = false;
    const u32 himask_tab[5] = {0u, 0xFF000000u, 0xFFFF0000u, 0xFFFFFF00u, 0xFFFFFFFFu};
    #pragma unroll
    for (int pass = 0; pass < 4; pass++) {
        if (!done) {
            const int shift = 24 - 8 * pass;
            const u32 hm = himask_tab[pass];
            #pragma unroll
            for (int j = 0; j < 4; j++)
                if ((v[j] & hm) == (prefix & hm)) atomicAdd(&hist[pass][(v[j] >> shift) & 255], 1);
            __syncthreads();
            if (t < 32) {
                u32 c[8], ssum = 0;
                #pragma unroll
                for (int j = 0; j < 8; j++) { c[j] = hist[pass][t * 8 + j]; ssum += c[j]; }
                u32 incl = ssum;
                #pragma unroll
                for (int o = 1; o < 32; o <<= 1) {
                    u32 n = __shfl_up_sync(FULL, incl, o);
                    if (lane >= o) incl += n;
                }
                u32 excl = incl - ssum;
                if (r >= excl && r < incl) {
                    u32 run = excl;
                    #pragma unroll
                    for (int j = 0; j < 8; j++) {
                        if (r < run + c[j]) {
                            bcast[0] = (u32)(t * 8 + j); bcast[1] = r - run; bcast[2] = c[j];
                            break;
                        }
                        run += c[j];
                    }
                }
            }
            __syncthreads();
            prefix |= bcast[0] << shift;
            r = bcast[1];
            if (pass < 3 && bcast[2] == 1) {
                // exactly one element carries this (pass+1)*8-bit prefix: it IS rank-511.
                const u32 fm = himask_tab[pass + 1];     // compile-time per unrolled pass
                #pragma unroll
                for (int j = 0; j < 4; j++)
                    if ((v[j] & fm) == prefix) s_D = v[j];
                __syncthreads();
                prefix = s_D;
                r = 0;
                done = true;
            }
        }
    }
    const u32 D = prefix;

    // fused scan: packed counters (f<<16)|lt
    u32 f[4], lt[4];
    u32 cnt = 0;
    #pragma unroll
    for (int j = 0; j < 4; j++) {
        f[j]  = (v[j] == D);
        lt[j] = (v[j] < D);
        cnt += (f[j] << 16) | lt[j];
    }
    u32 incl = cnt;
    #pragma unroll
    for (int o = 1; o < 32; o <<= 1) {
        u32 n = __shfl_up_sync(FULL, incl, o);
        if (lane >= o) incl += n;
    }
    if (lane == 31) warpsum[w] = incl;
    __syncthreads();
    if (t == 0) { u32 run = 0; for (int j = 0; j < 8; j++) { u32 tmp = warpsum[j]; warpsum[j] = run; run += tmp; } }
    __syncthreads();
    u32 excl = warpsum[w] + (incl - cnt);
    u32 pf  = excl >> 16;
    u32 plt = excl & 0xFFFFu;

    float4* outp = g_selp + (size_t)b * KPOS;
    u64 key = 0xFFFFFFFFFFFFFFFFull;
    #pragma unroll
    for (int j = 0; j < 4; j++) {
        u32 m = lt[j] | (f[j] & (pf <= r));
        if (m) {
            u32 slot = plt + min(pf, r + 1u);
            outp[slot] = make_float4(fpx[j], fpy[j], fpz[j], (float)(i0 + j));
            key = umin64(key, ((u64)v[j] << 32) | slot);
        }
        pf += f[j];
        plt += lt[j];
    }
    #pragma unroll
    for (int o = 16; o >= 1; o >>= 1)
        key = umin64(key, shfl_xor_u64(key, o));
    if (lane == 0) warpkey[w] = key;
    __syncthreads();
    if (t == 0) {
        u64 k = warpkey[0];
        #pragma unroll
        for (int j = 1; j < 8; j++) k = umin64(k, warpkey[j]);
        g_start[b] = (int)(u32)k;
    }
}

// ---------------- K2: FPS (2 warps, packed f32x2) + fused MLP [round-13 verbatim + PDL] ----------------
__global__ __launch_bounds__(64) void fps_mlp_kernel(
    const float* __restrict__ x,
    const float* __restrict__ W1, const float* __restrict__ b1,
    const float* __restrict__ W2, const float* __restrict__ b2,
    const float* __restrict__ W3, const float* __restrict__ b3,
    float* __restrict__ out_w, float* __restrict__ out_i)
{
    __shared__ float4 selp[KPOS];
    __shared__ int chosen[KSEL];
    __shared__ float wsh[WTOT];
    __shared__ u64 sred[2][2];

    const int b = blockIdx.x;
    const int t = threadIdx.x;
    const int l = t & 31, w = t >> 5;
    const unsigned FULL = 0xffffffffu;

    for (int i = t; i < WTOT; i += 64) {
        float v;
        if (i < B1_OFF)       v = W1[i];
        else if (i < W2_OFF)  v = b1[i - B1_OFF];
        else if (i < B2_OFF)  v = W2[i - W2_OFF];
        else if (i < W3_OFF)  v = b2[i - B2_OFF];
        else if (i < B3_OFF)  v = W3[i - W3_OFF];
        else                  v = b3[0];
        wsh[i] = v;
    }

    cudaGridDependencySynchronize();

    float fx[8], fy[8], fz[8];
    #pragma unroll
    for (int m = 0; m < 8; m++) {
        int slot = (w << 8) + (m << 5) + l;
        float4 f = g_selp[(size_t)b * KPOS + slot];
        selp[slot] = f;
        fx[m] = f.x; fy[m] = f.y; fz[m] = f.z;
    }
    u64 PX[4], PY[4], PZ[4];
    #pragma unroll
    for (int p = 0; p < 4; p++) {
        PACK_F32X2(PX[p], __float_as_uint(fx[2 * p]), __float_as_uint(fx[2 * p + 1]));
        PACK_F32X2(PY[p], __float_as_uint(fy[2 * p]), __float_as_uint(fy[2 * p + 1]));
        PACK_F32X2(PZ[p], __float_as_uint(fz[2 * p]), __float_as_uint(fz[2 * p + 1]));
    }
    __syncthreads();

    const int sslot = g_start[b];
    float4 p0 = selp[sslot];
    if (t == 0) {
        out_i[(size_t)b * KSEL + 0] = p0.w;
        chosen[0] = (int)p0.w;
    }

    u64 NX, NY, NZ;
    {
        u32 nx = __float_as_uint(-p0.x), ny = __float_as_uint(-p0.y), nz = __float_as_uint(-p0.z);
        PACK_F32X2(NX, nx, nx); PACK_F32X2(NY, ny, ny); PACK_F32X2(NZ, nz, nz);
    }
    u64 md[4];
    #pragma unroll
    for (int p = 0; p < 4; p++) {
        u64 dx, dy, dz, xx, yy, zz, s1, s2;
        ADD_F32X2(dx, PX[p], NX); ADD_F32X2(dy, PY[p], NY); ADD_F32X2(dz, PZ[p], NZ);
        MUL_F32X2(xx, dx, dx); MUL_F32X2(yy, dy, dy); MUL_F32X2(zz, dz, dz);
        ADD_F32X2(s1, xx, yy); ADD_F32X2(s2, s1, zz);
        md[p] = s2;
    }

    const u32 rc = 511u - (u32)(w * 256) - (u32)l;

    for (int it = 1; it < KSEL; ++it) {
        u32 bl0 = (u32)md[0], bh0 = (u32)(md[0] >> 32);
        u32 bl1 = (u32)md[1], bh1 = (u32)(md[1] >> 32);
        u32 bl2 = (u32)md[2], bh2 = (u32)(md[2] >> 32);
        u32 bl3 = (u32)md[3], bh3 = (u32)(md[3] >> 32);
        u32 a0 = max(bl0, bh0), a1 = max(bl1, bh1), a2 = max(bl2, bh2), a3 = max(bl3, bh3);
        u32 lmax = max(max(a0, a1), max(a2, a3));
        u32 wmax = __reduce_max_sync(FULL, lmax);

        u32 c0 = (bl0 == wmax) ? (rc - 0)   : 0u;
        u32 c1 = (bh0 == wmax) ? (rc - 32)  : 0u;
        u32 c2 = (bl1 == wmax) ? (rc - 64)  : 0u;
        u32 c3 = (bh1 == wmax) ? (rc - 96)  : 0u;
        u32 c4 = (bl2 == wmax) ? (rc - 128) : 0u;
        u32 c5 = (bh2 == wmax) ? (rc - 160) : 0u;
        u32 c6 = (bl3 == wmax) ? (rc - 192) : 0u;
        u32 c7 = (bh3 == wmax) ? (rc - 224) : 0u;
        u32 cm = max(max(max(c0, c1), max(c2, c3)), max(max(c4, c5), max(c6, c7)));
        u32 wcand = __reduce_max_sync(FULL, cm);

        if (l == 0) sred[w][it & 1] = ((u64)wmax << 32) | wcand;
        __syncthreads();
        u64 best = umax64(sred[0][it & 1], sred[1][it & 1]);
        int sel = 511 - (int)(u32)best;

        float4 c = selp[sel];
        if (t == 0) {
            out_i[(size_t)b * KSEL + it] = c.w;
            chosen[it] = (int)c.w;
        }

        u32 nx = __float_as_uint(-c.x), ny = __float_as_uint(-c.y), nz = __float_as_uint(-c.z);
        PACK_F32X2(NX, nx, nx); PACK_F32X2(NY, ny, ny); PACK_F32X2(NZ, nz, nz);
        #pragma unroll
        for (int p = 0; p < 4; p++) {
            u64 dx, dy, dz, xx, yy, zz, s1, s2;
            ADD_F32X2(dx, PX[p], NX); ADD_F32X2(dy, PY[p], NY); ADD_F32X2(dz, PZ[p], NZ);
            MUL_F32X2(xx, dx, dx); MUL_F32X2(yy, dy, dy); MUL_F32X2(zz, dz, dz);
            ADD_F32X2(s1, xx, yy); ADD_F32X2(s2, s1, zz);
            u32 mlo = min((u32)md[p], (u32)s2);
            u32 mhi = min((u32)(md[p] >> 32), (u32)(s2 >> 32));
            md[p] = ((u64)mhi << 32) | mlo;
        }
    }
    __syncthreads();

    if (t < KSEL) {
        int orig = chosen[t];
        const float4* xr4 = (const float4*)(x + ((size_t)b * NPTS + orig) * 32);
        float xv[32];
        #pragma unroll
        for (int i = 0; i < 8; i++) {
            float4 q = xr4[i];
            xv[4 * i] = q.x; xv[4 * i + 1] = q.y; xv[4 * i + 2] = q.z; xv[4 * i + 3] = q.w;
        }

        float h1v[16];
        #pragma unroll
        for (int o = 0; o < 16; o++) {
            float a = wsh[B1_OFF + o];
            #pragma unroll
            for (int i = 0; i < 32; i++) a = fmaf(xv[i], wsh[W1_OFF + i * 16 + o], a);
            h1v[o] = fmaxf(a, 0.0f);
        }
        float h2v[8];
        #pragma unroll
        for (int o = 0; o < 8; o++) {
            float a = wsh[B2_OFF + o];
            #pragma unroll
            for (int i = 0; i < 16; i++) a = fmaf(h1v[i], wsh[W2_OFF + i * 8 + o], a);
            h2v[o] = fmaxf(a, 0.0f);
        }
        float s = wsh[B3_OFF];
        #pragma unroll
        for (int i = 0; i < 8; i++) s = fmaf(h2v[i], wsh[W3_OFF + i], s);
        float sp = fmaxf(s, 0.0f) + log1pf(expf(-fabsf(s)));
        out_w[(size_t)b * KSEL + t] = sp;
    }
}

extern "C" void kernel_launch(void* const* d_in, const int* in_sizes, int n_in,
                              void* d_out, int out_size) {
    const float* x   = (const float*)d_in[0];
    const float* pos = (const float*)d_in[1];
    const float* W1  = (const float*)d_in[3];
    const float* b1  = (const float*)d_in[4];
    const float* W2  = (const float*)d_in[5];
    const float* b2  = (const float*)d_in[6];
    const float* W3  = (const float*)d_in[7];
    const float* b3  = (const float*)d_in[8];

    int n_points = in_sizes[0] / 32;      // B * 1024
    int B = n_points / NPTS;
    if (B > BMAX) B = BMAX;

    float* out_w = (float*)d_out;
    float* out_i = out_w + (size_t)B * KSEL;

    select_kernel<<<B, T1>>>(pos);

    cudaLaunchConfig_t cfg = {};
    cfg.gridDim = dim3((unsigned)B);
    cfg.blockDim = dim3(64);
    cfg.dynamicSmemBytes = 0;
    cfg.stream = 0;
    cudaLaunchAttribute attr[1];
    attr[0].id = cudaLaunchAttributeProgrammaticStreamSerialization;
    attr[0].val.programmaticStreamSerializationAllowed = 1;
    cfg.attrs = attr;
    cfg.numAttrs = 1;
    cudaLaunchKernelEx(&cfg, fps_mlp_kernel, x, W1, b1, W2, b2, W3, b3, out_w, out_i);
}

// round 17
// speedup vs baseline: 1.1048x; 1.0528x over previous
#include <cuda_runtime.h>
#include <cuda_bf16.h>
#include <math.h>

// Detector: per-submap (1024 pts) -> top-512 by xy-dist -> FPS 32 -> MLP gather.
// K1: register-resident radix-select + singleton early exit; compacted points staged in
//     SHARED then flushed with coalesced STG.128 (was: scattered global stores).
// K2: 2 warps/submap packed-f32x2 FPS (8 pts/lane) + fused MLP [round-6/13 optimum], PDL launch.

#define NPTS 1024
#define KPOS 512
#define KSEL 32
#define T1   256
#define BMAX 2048

#define W1_OFF 0
#define B1_OFF 512
#define W2_OFF 528
#define B2_OFF 656
#define W3_OFF 664
#define B3_OFF 672
#define WTOT   673

typedef unsigned long long u64;
typedef unsigned int u32;

__device__ float4 g_selp[(size_t)BMAX * KPOS];
__device__ int    g_start[BMAX];

__device__ __forceinline__ u64 umax64(u64 a, u64 b) { return a > b ? a : b; }
__device__ __forceinline__ u64 umin64(u64 a, u64 b) { return a < b ? a : b; }

__device__ __forceinline__ u64 shfl_xor_u64(u64 v, int m) {
    u32 lo = __shfl_xor_sync(0xffffffffu, (u32)v, m);
    u32 hi = __shfl_xor_sync(0xffffffffu, (u32)(v >> 32), m);
    return ((u64)hi << 32) | lo;
}

#define PACK_F32X2(out, lo, hi) \
    asm("mov.b64 %0, {%1, %2};" : "=l"(out) : "r"(lo), "r"(hi))
#define ADD_F32X2(out, a, b) \
    asm("add.rn.f32x2 %0, %1, %2;" : "=l"(out) : "l"(a), "l"(b))
#define MUL_F32X2(out, a, b) \
    asm("mul.rn.f32x2 %0, %1, %2;" : "=l"(out) : "l"(a), "l"(b))

// ---------------- K1: select top-512 + compact ----------------
__global__ __launch_bounds__(T1) void select_kernel(const float* __restrict__ pos)
{
    __shared__ u32 hist[4][256];
    __shared__ float4 sselp[KPOS];    // staged compacted points (8 KB)
    __shared__ u32 warpsum[8];
    __shared__ u64 warpkey[8];
    __shared__ u32 bcast[3];          // [byte, r, count]
    __shared__ u32 s_D;

    const int b = blockIdx.x, t = threadIdx.x;
    const int lane = t & 31, w = t >> 5;
    const size_t base = (size_t)b * NPTS;
    const unsigned FULL = 0xffffffffu;

    {
        u32* h = (u32*)hist;
        #pragma unroll
        for (int j = 0; j < 4; j++) h[j * T1 + t] = 0;
    }

    const int i0 = t * 4;
    float fpx[4], fpy[4], fpz[4];
    {
        const float4* p4 = (const float4*)(pos + base * 3);
        float4 q0 = p4[t * 3 + 0];
        float4 q1 = p4[t * 3 + 1];
        float4 q2 = p4[t * 3 + 2];
        fpx[0] = q0.x; fpy[0] = q0.y; fpz[0] = q0.z;
        fpx[1] = q0.w; fpy[1] = q1.x; fpz[1] = q1.y;
        fpx[2] = q1.z; fpy[2] = q1.w; fpz[2] = q2.x;
        fpx[3] = q2.y; fpy[3] = q2.z; fpz[3] = q2.w;
    }
    u32 v[4];
    #pragma unroll
    for (int j = 0; j < 4; j++)
        v[j] = __float_as_uint(__fsqrt_rn(__fadd_rn(__fmul_rn(fpx[j], fpx[j]),
                                                    __fmul_rn(fpy[j], fpy[j]))));
    __syncthreads();

    // radix select rank-511; singleton early exit (block-uniform control, static shifts)
    u32 r = 511, prefix = 0;
    bool done = false;
    const u32 himask_tab[5] = {0u, 0xFF000000u, 0xFFFF0000u, 0xFFFFFF00u, 0xFFFFFFFFu};
    #pragma unroll
    for (int pass = 0; pass < 4; pass++) {
        if (!done) {
            const int shift = 24 - 8 * pass;
            const u32 hm = himask_tab[pass];
            #pragma unroll
            for (int j = 0; j < 4; j++)
                if ((v[j] & hm) == (prefix & hm)) atomicAdd(&hist[pass][(v[j] >> shift) & 255], 1);
            __syncthreads();
            if (t < 32) {
                u32 c[8], ssum = 0;
                #pragma unroll
                for (int j = 0; j < 8; j++) { c[j] = hist[pass][t * 8 + j]; ssum += c[j]; }
                u32 incl = ssum;
                #pragma unroll
                for (int o = 1; o < 32; o <<= 1) {
                    u32 n = __shfl_up_sync(FULL, incl, o);
                    if (lane >= o) incl += n;
                }
                u32 excl = incl - ssum;
                if (r >= excl && r < incl) {
                    u32 run = excl;
                    #pragma unroll
                    for (int j = 0; j < 8; j++) {
                        if (r < run + c[j]) {
                            bcast[0] = (u32)(t * 8 + j); bcast[1] = r - run; bcast[2] = c[j];
                            break;
                        }
                        run += c[j];
                    }
                }
            }
            __syncthreads();
            prefix |= bcast[0] << shift;
            r = bcast[1];
            if (pass < 3 && bcast[2] == 1) {
                const u32 fm = himask_tab[pass + 1];
                #pragma unroll
                for (int j = 0; j < 4; j++)
                    if ((v[j] & fm) == prefix) s_D = v[j];
                __syncthreads();
                prefix = s_D;
                r = 0;
                done = true;
            }
        }
    }
    const u32 D = prefix;

    // fused scan: packed counters (f<<16)|lt
    u32 f[4], lt[4];
    u32 cnt = 0;
    #pragma unroll
    for (int j = 0; j < 4; j++) {
        f[j]  = (v[j] == D);
        lt[j] = (v[j] < D);
        cnt += (f[j] << 16) | lt[j];
    }
    u32 incl = cnt;
    #pragma unroll
    for (int o = 1; o < 32; o <<= 1) {
        u32 n = __shfl_up_sync(FULL, incl, o);
        if (lane >= o) incl += n;
    }
    if (lane == 31) warpsum[w] = incl;
    __syncthreads();
    if (t == 0) { u32 run = 0; for (int j = 0; j < 8; j++) { u32 tmp = warpsum[j]; warpsum[j] = run; run += tmp; } }
    __syncthreads();
    u32 excl = warpsum[w] + (incl - cnt);
    u32 pf  = excl >> 16;
    u32 plt = excl & 0xFFFFu;

    // stage members in shared (scattered STS), track start key
    u64 key = 0xFFFFFFFFFFFFFFFFull;
    #pragma unroll
    for (int j = 0; j < 4; j++) {
        u32 m = lt[j] | (f[j] & (pf <= r));
        if (m) {
            u32 slot = plt + min(pf, r + 1u);
            sselp[slot] = make_float4(fpx[j], fpy[j], fpz[j], (float)(i0 + j));
            key = umin64(key, ((u64)v[j] << 32) | slot);
        }
        pf += f[j];
        plt += lt[j];
    }
    #pragma unroll
    for (int o = 16; o >= 1; o >>= 1)
        key = umin64(key, shfl_xor_u64(key, o));
    if (lane == 0) warpkey[w] = key;
    __syncthreads();   // sselp complete + warpkey visible
    if (t == 0) {
        u64 k = warpkey[0];
        #pragma unroll
        for (int j = 1; j < 8; j++) k = umin64(k, warpkey[j]);
        g_start[b] = (int)(u32)k;
    }

    // coalesced flush: thread t writes slots t and t+256 (perfect 128B-line streams)
    float4* outp = g_selp + (size_t)b * KPOS;
    outp[t]       = sselp[t];
    outp[t + 256] = sselp[t + 256];
}

// ---------------- K2: FPS (2 warps, packed f32x2) + fused MLP [round-13 verbatim + PDL] ----------------
__global__ __launch_bounds__(64) void fps_mlp_kernel(
    const float* __restrict__ x,
    const float* __restrict__ W1, const float* __restrict__ b1,
    const float* __restrict__ W2, const float* __restrict__ b2,
    const float* __restrict__ W3, const float* __restrict__ b3,
    float* __restrict__ out_w, float* __restrict__ out_i)
{
    __shared__ float4 selp[KPOS];
    __shared__ int chosen[KSEL];
    __shared__ float wsh[WTOT];
    __shared__ u64 sred[2][2];

    const int b = blockIdx.x;
    const int t = threadIdx.x;
    const int l = t & 31, w = t >> 5;
    const unsigned FULL = 0xffffffffu;

    for (int i = t; i < WTOT; i += 64) {
        float v;
        if (i < B1_OFF)       v = W1[i];
        else if (i < W2_OFF)  v = b1[i - B1_OFF];
        else if (i < B2_OFF)  v = W2[i - W2_OFF];
        else if (i < W3_OFF)  v = b2[i - B2_OFF];
        else if (i < B3_OFF)  v = W3[i - W3_OFF];
        else                  v = b3[0];
        wsh[i] = v;
    }

    cudaGridDependencySynchronize();

    float fx[8], fy[8], fz[8];
    #pragma unroll
    for (int m = 0; m < 8; m++) {
        int slot = (w << 8) + (m << 5) + l;
        float4 f = g_selp[(size_t)b * KPOS + slot];
        selp[slot] = f;
        fx[m] = f.x; fy[m] = f.y; fz[m] = f.z;
    }
    u64 PX[4], PY[4], PZ[4];
    #pragma unroll
    for (int p = 0; p < 4; p++) {
        PACK_F32X2(PX[p], __float_as_uint(fx[2 * p]), __float_as_uint(fx[2 * p + 1]));
        PACK_F32X2(PY[p], __float_as_uint(fy[2 * p]), __float_as_uint(fy[2 * p + 1]));
        PACK_F32X2(PZ[p], __float_as_uint(fz[2 * p]), __float_as_uint(fz[2 * p + 1]));
    }
    __syncthreads();

    const int sslot = g_start[b];
    float4 p0 = selp[sslot];
    if (t == 0) {
        out_i[(size_t)b * KSEL + 0] = p0.w;
        chosen[0] = (int)p0.w;
    }

    u64 NX, NY, NZ;
    {
        u32 nx = __float_as_uint(-p0.x), ny = __float_as_uint(-p0.y), nz = __float_as_uint(-p0.z);
        PACK_F32X2(NX, nx, nx); PACK_F32X2(NY, ny, ny); PACK_F32X2(NZ, nz, nz);
    }
    u64 md[4];
    #pragma unroll
    for (int p = 0; p < 4; p++) {
        u64 dx, dy, dz, xx, yy, zz, s1, s2;
        ADD_F32X2(dx, PX[p], NX); ADD_F32X2(dy, PY[p], NY); ADD_F32X2(dz, PZ[p], NZ);
        MUL_F32X2(xx, dx, dx); MUL_F32X2(yy, dy, dy); MUL_F32X2(zz, dz, dz);
        ADD_F32X2(s1, xx, yy); ADD_F32X2(s2, s1, zz);
        md[p] = s2;
    }

    const u32 rc = 511u - (u32)(w * 256) - (u32)l;

    for (int it = 1; it < KSEL; ++it) {
        u32 bl0 = (u32)md[0], bh0 = (u32)(md[0] >> 32);
        u32 bl1 = (u32)md[1], bh1 = (u32)(md[1] >> 32);
        u32 bl2 = (u32)md[2], bh2 = (u32)(md[2] >> 32);
        u32 bl3 = (u32)md[3], bh3 = (u32)(md[3] >> 32);
        u32 a0 = max(bl0, bh0), a1 = max(bl1, bh1), a2 = max(bl2, bh2), a3 = max(bl3, bh3);
        u32 lmax = max(max(a0, a1), max(a2, a3));
        u32 wmax = __reduce_max_sync(FULL, lmax);

        u32 c0 = (bl0 == wmax) ? (rc - 0)   : 0u;
        u32 c1 = (bh0 == wmax) ? (rc - 32)  : 0u;
        u32 c2 = (bl1 == wmax) ? (rc - 64)  : 0u;
        u32 c3 = (bh1 == wmax) ? (rc - 96)  : 0u;
        u32 c4 = (bl2 == wmax) ? (rc - 128) : 0u;
        u32 c5 = (bh2 == wmax) ? (rc - 160) : 0u;
        u32 c6 = (bl3 == wmax) ? (rc - 192) : 0u;
        u32 c7 = (bh3 == wmax) ? (rc - 224) : 0u;
        u32 cm = max(max(max(c0, c1), max(c2, c3)), max(max(c4, c5), max(c6, c7)));
        u32 wcand = __reduce_max_sync(FULL, cm);

        if (l == 0) sred[w][it & 1] = ((u64)wmax << 32) | wcand;
        __syncthreads();
        u64 best = umax64(sred[0][it & 1], sred[1][it & 1]);
        int sel = 511 - (int)(u32)best;

        float4 c = selp[sel];
        if (t == 0) {
            out_i[(size_t)b * KSEL + it] = c.w;
            chosen[it] = (int)c.w;
        }

        u32 nx = __float_as_uint(-c.x), ny = __float_as_uint(-c.y), nz = __float_as_uint(-c.z);
        PACK_F32X2(NX, nx, nx); PACK_F32X2(NY, ny, ny); PACK_F32X2(NZ, nz, nz);
        #pragma unroll
        for (int p = 0; p < 4; p++) {
            u64 dx, dy, dz, xx, yy, zz, s1, s2;
            ADD_F32X2(dx, PX[p], NX); ADD_F32X2(dy, PY[p], NY); ADD_F32X2(dz, PZ[p], NZ);
            MUL_F32X2(xx, dx, dx); MUL_F32X2(yy, dy, dy); MUL_F32X2(zz, dz, dz);
            ADD_F32X2(s1, xx, yy); ADD_F32X2(s2, s1, zz);
            u32 mlo = min((u32)md[p], (u32)s2);
            u32 mhi = min((u32)(md[p] >> 32), (u32)(s2 >> 32));
            md[p] = ((u64)mhi << 32) | mlo;
        }
    }
    __syncthreads();

    if (t < KSEL) {
        int orig = chosen[t];
        const float4* xr4 = (const float4*)(x + ((size_t)b * NPTS + orig) * 32);
        float xv[32];
        #pragma unroll
        for (int i = 0; i < 8; i++) {
            float4 q = xr4[i];
            xv[4 * i] = q.x; xv[4 * i + 1] = q.y; xv[4 * i + 2] = q.z; xv[4 * i + 3] = q.w;
        }

        float h1v[16];
        #pragma unroll
        for (int o = 0; o < 16; o++) {
            float a = wsh[B1_OFF + o];
            #pragma unroll
            for (int i = 0; i < 32; i++) a = fmaf(xv[i], wsh[W1_OFF + i * 16 + o], a);
            h1v[o] = fmaxf(a, 0.0f);
        }
        float h2v[8];
        #pragma unroll
        for (int o = 0; o < 8; o++) {
            float a = wsh[B2_OFF + o];
            #pragma unroll
            for (int i = 0; i < 16; i++) a = fmaf(h1v[i], wsh[W2_OFF + i * 8 + o], a);
            h2v[o] = fmaxf(a, 0.0f);
        }
        float s = wsh[B3_OFF];
        #pragma unroll
        for (int i = 0; i < 8; i++) s = fmaf(h2v[i], wsh[W3_OFF + i], s);
        float sp = fmaxf(s, 0.0f) + log1pf(expf(-fabsf(s)));
        out_w[(size_t)b * KSEL + t] = sp;
    }
}

extern "C" void kernel_launch(void* const* d_in, const int* in_sizes, int n_in,
                              void* d_out, int out_size) {
    const float* x   = (const float*)d_in[0];
    const float* pos = (const float*)d_in[1];
    const float* W1  = (const float*)d_in[3];
    const float* b1  = (const float*)d_in[4];
    const float* W2  = (const float*)d_in[5];
    const float* b2  = (const float*)d_in[6];
    const float* W3  = (const float*)d_in[7];
    const float* b3  = (const float*)d_in[8];

    int n_points = in_sizes[0] / 32;      // B * 1024
    int B = n_points / NPTS;
    if (B > BMAX) B = BMAX;

    float* out_w = (float*)d_out;
    float* out_i = out_w + (size_t)B * KSEL;

    select_kernel<<<B, T1>>>(pos);

    cudaLaunchConfig_t cfg = {};
    cfg.gridDim = dim3((unsigned)B);
    cfg.blockDim = dim3(64);
    cfg.dynamicSmemBytes = 0;
    cfg.stream = 0;
    cudaLaunchAttribute attr[1];
    attr[0].id = cudaLaunchAttributeProgrammaticStreamSerialization;
    attr[0].val.programmaticStreamSerializationAllowed = 1;
    cfg.attrs = attr;
    cfg.numAttrs = 1;
    cudaLaunchKernelEx(&cfg, fps_mlp_kernel, x, W1, b1, W2, b2, W3, b3, out_w, out_i);
}